// round 15
// baseline (speedup 1.0000x reference)
#include <cuda_runtime.h>
#include <cuda_bf16.h>
#include <mma.h>
#include <math.h>

using namespace nvcuda;

#define NTOK   8192
#define DMODEL 1024
#define DI     2048
#define DS     16
#define LSEQ   2048
#define BATCH  4
#define DTR    64
#define DBCW   96

// ---------------- scratch: round-3 proven set ----------------
__device__ __align__(256) float g_scale[NTOK];
__device__ __align__(256) float g_xi   [(size_t)NTOK * DI];    // xi -> later y
__device__ __align__(256) float g_u    [(size_t)NTOK * DI];    // silu(conv)
__device__ __align__(256) float g_z    [(size_t)NTOK * DI];    // gate branch
__device__ __align__(256) float g_dbc  [(size_t)NTOK * DBCW];  // x_proj out
__device__ __align__(256) float g_delta[(size_t)NTOK * DI];    // softplus

__device__ __forceinline__ float siluf(float v) { return v / (1.f + __expf(-v)); }

// ---------------- RMS scale per token ----------------
__global__ void rms_kernel(const float* __restrict__ x) {
    int t = blockIdx.x;
    const float* row = x + (size_t)t * DMODEL;
    float s = 0.f;
    for (int i = threadIdx.x; i < DMODEL; i += 256) { float v = row[i]; s += v * v; }
    #pragma unroll
    for (int o = 16; o; o >>= 1) s += __shfl_xor_sync(0xffffffffu, s, o);
    __shared__ float sm[8];
    if ((threadIdx.x & 31) == 0) sm[threadIdx.x >> 5] = s;
    __syncthreads();
    if (threadIdx.x == 0) {
        float tot = 0.f;
        #pragma unroll
        for (int i = 0; i < 8; i++) tot += sm[i];
        g_scale[t] = rsqrtf(tot / (float)DMODEL + 1e-5f);
    }
}

// ---------------- tf32 wmma GEMM, register-prefetch pipeline ----------------
// C = A(MxK) * B(NxK)^T
// SRC: 0 ext | 1 g_u | 2 g_dbc | 3 g_xi
// AMODE: 0 plain | 1 A*g_scale[row]*colw (rmsnorm) | 2 A*silu(g_z) (gate)
// EPI: 0 split -> g_xi / g_z | 1 -> g_dbc | 2 softplus(acc+epivec[c]) -> g_delta
//      3 acc + epivec[r*ldc+c] -> outext
template<int SRC, int AMODE, int EPI>
__global__ void __launch_bounds__(256)
gemm_tf32(const float* __restrict__ Aext, const float* __restrict__ Bw,
          int N, int K, int lda,
          const float* __restrict__ colw,
          float* __restrict__ outext,
          int ldc, const float* __restrict__ epivec)
{
    constexpr int BM = 128, BN = 64, BK = 32, LDT = 36;
    __shared__ __align__(16) float sPool[(BM + BN) * LDT];   // 27648 B
    float* sA = sPool;                 // 128 x 36
    float* sB = sPool + BM * LDT;      // 64 x 36
    float* sC = sPool;                 // epilogue alias: 128 x 32

    const float* A = (SRC == 0) ? Aext : (SRC == 1) ? g_u : (SRC == 2) ? g_dbc : g_xi;

    const int tid = threadIdx.x;
    const int bm = blockIdx.y, bn = blockIdx.x;
    const int warp = tid >> 5;
    const int wm = warp >> 1, wn = warp & 1;   // 4 x 2 warps, each 32x32

    wmma::fragment<wmma::accumulator, 16, 16, 8, float> acc[2][2];
    #pragma unroll
    for (int i = 0; i < 2; i++)
        #pragma unroll
        for (int j = 0; j < 2; j++) wmma::fill_fragment(acc[i][j], 0.f);

    // A staging: row = tid>>1 (0..127), 16 cols at (tid&1)*16
    const int ar = tid >> 1;
    const int ac = (tid & 1) * 16;
    const int argr = bm * BM + ar;
    const float rs = (AMODE == 1) ? g_scale[argr] : 0.f;
    const float* aRow = A + (size_t)argr * lda;
    const float* zRow = (AMODE == 2) ? (g_z + (size_t)argr * lda) : nullptr;
    // B staging: thread covers 2 float4 chunks q = tid*2+{0,1}
    const int bn0 = (tid * 2) >> 3, bc0 = ((tid * 2) & 7) * 4;
    const int bn1 = (tid * 2 + 1) >> 3, bc1 = ((tid * 2 + 1) & 7) * 4;
    const int ngc0 = (bn * BN + bn0 < N) ? bn * BN + bn0 : N - 1;
    const int ngc1 = (bn * BN + bn1 < N) ? bn * BN + bn1 : N - 1;
    const float* bRow0 = Bw + (size_t)ngc0 * K;
    const float* bRow1 = Bw + (size_t)ngc1 * K;

    float4 pa[4], pb[2];

#define DO_LDG(K0_) {                                                             \
    _Pragma("unroll")                                                             \
    for (int i_ = 0; i_ < 4; i_++) {                                              \
        int c_ = ac + i_ * 4;                                                     \
        float4 v_ = *reinterpret_cast<const float4*>(aRow + (K0_) + c_);          \
        if (AMODE == 1) {                                                         \
            float4 w_ = *reinterpret_cast<const float4*>(colw + (K0_) + c_);      \
            v_.x *= rs * w_.x; v_.y *= rs * w_.y;                                 \
            v_.z *= rs * w_.z; v_.w *= rs * w_.w;                                 \
        } else if (AMODE == 2) {                                                  \
            float4 z_ = *reinterpret_cast<const float4*>(zRow + (K0_) + c_);      \
            v_.x *= siluf(z_.x); v_.y *= siluf(z_.y);                             \
            v_.z *= siluf(z_.z); v_.w *= siluf(z_.w);                             \
        }                                                                         \
        pa[i_] = v_;                                                              \
    }                                                                             \
    pb[0] = *reinterpret_cast<const float4*>(bRow0 + (K0_) + bc0);                \
    pb[1] = *reinterpret_cast<const float4*>(bRow1 + (K0_) + bc1);                \
}

#define DO_STS() {                                                                \
    _Pragma("unroll")                                                             \
    for (int i_ = 0; i_ < 4; i_++)                                                \
        *reinterpret_cast<float4*>(&sA[ar * LDT + ac + i_ * 4]) = pa[i_];         \
    *reinterpret_cast<float4*>(&sB[bn0 * LDT + bc0]) = pb[0];                     \
    *reinterpret_cast<float4*>(&sB[bn1 * LDT + bc1]) = pb[1];                     \
}

    const int KT = K / BK;
    DO_LDG(0);

    for (int kt = 0; kt < KT; kt++) {
        DO_STS();
        __syncthreads();
        if (kt + 1 < KT) DO_LDG((kt + 1) * BK);   // overlap next-tile LDG with compute

        #pragma unroll
        for (int kk = 0; kk < BK; kk += 8) {
            wmma::fragment<wmma::matrix_a, 16, 16, 8, wmma::precision::tf32, wmma::row_major> fa[2];
            wmma::fragment<wmma::matrix_b, 16, 16, 8, wmma::precision::tf32, wmma::col_major> fb[2];
            #pragma unroll
            for (int i = 0; i < 2; i++) {
                wmma::load_matrix_sync(fa[i], &sA[(wm * 32 + i * 16) * LDT + kk], LDT);
                #pragma unroll
                for (int e = 0; e < fa[i].num_elements; e++)
                    fa[i].x[e] = wmma::__float_to_tf32(fa[i].x[e]);
            }
            #pragma unroll
            for (int j = 0; j < 2; j++) {
                wmma::load_matrix_sync(fb[j], &sB[(wn * 32 + j * 16) * LDT + kk], LDT);
                #pragma unroll
                for (int e = 0; e < fb[j].num_elements; e++)
                    fb[j].x[e] = wmma::__float_to_tf32(fb[j].x[e]);
            }
            #pragma unroll
            for (int i = 0; i < 2; i++)
                #pragma unroll
                for (int j = 0; j < 2; j++)
                    wmma::mma_sync(acc[i][j], fa[i], fb[j], acc[i][j]);
        }
        __syncthreads();
    }
#undef DO_LDG
#undef DO_STS

    // epilogue: two 32-col chunks through aliased sC (128 x 32)
    #pragma unroll
    for (int h = 0; h < 2; h++) {
        if (wn == h) {
            #pragma unroll
            for (int i = 0; i < 2; i++)
                #pragma unroll
                for (int j = 0; j < 2; j++)
                    wmma::store_matrix_sync(&sC[(wm * 32 + i * 16) * 32 + j * 16],
                                            acc[i][j], 32, wmma::mem_row_major);
        }
        __syncthreads();
        for (int e = tid; e < BM * 32; e += 256) {
            int r = e >> 5, c = e & 31;
            int rg = bm * BM + r;
            int cg = bn * BN + h * 32 + c;
            if (cg < N) {
                float v = sC[e];
                if (EPI == 0) {
                    if (cg < DI) g_xi[(size_t)rg * DI + cg] = v;
                    else         g_z [(size_t)rg * DI + cg - DI] = v;
                } else if (EPI == 1) {
                    g_dbc[(size_t)rg * DBCW + cg] = v;
                } else if (EPI == 2) {
                    float t2 = v + epivec[cg];
                    g_delta[(size_t)rg * DI + cg] = (t2 > 20.f) ? t2 : log1pf(__expf(t2));
                } else {
                    outext[(size_t)rg * ldc + cg] = v + epivec[(size_t)rg * ldc + cg];
                }
            }
        }
        __syncthreads();
    }
}

// ---------------- causal depthwise conv (k=4) + bias + SiLU ----------------
__global__ void conv_silu_kernel(const float* __restrict__ cw, const float* __restrict__ cb) {
    int c  = blockIdx.x * 256 + threadIdx.x;
    int b  = blockIdx.z;
    int t0 = blockIdx.y * 8;
    float w0 = cw[c * 4 + 0], w1 = cw[c * 4 + 1], w2 = cw[c * 4 + 2], w3 = cw[c * 4 + 3];
    float bias = cb[c];
    float v[11];
    #pragma unroll
    for (int q = 0; q < 11; q++) {
        int t = t0 - 3 + q;
        v[q] = (t >= 0) ? g_xi[((size_t)(b * LSEQ + t)) * DI + c] : 0.f;
    }
    #pragma unroll
    for (int tt = 0; tt < 8; tt++) {
        float o = w0 * v[tt] + w1 * v[tt + 1] + w2 * v[tt + 2] + w3 * v[tt + 3] + bias;
        g_u[((size_t)(b * LSEQ + t0 + tt)) * DI + c] = siluf(o);
    }
}

// ---------------- selective scan (y -> g_xi) ----------------
__global__ void scan_kernel(const float* __restrict__ A_log, const float* __restrict__ Dp) {
    int b    = blockIdx.y;
    int lane = threadIdx.x & 31, warp = threadIdx.x >> 5;
    int chan_local = warp * 4 + (lane >> 3);
    int j = lane & 7;
    int d = blockIdx.x * 32 + chan_local;

    float A0 = -__expf(A_log[d * DS + 2 * j]);
    float A1 = -__expf(A_log[d * DS + 2 * j + 1]);
    float Dd = Dp[d];
    float s0 = 0.f, s1 = 0.f;

    size_t idx = ((size_t)b * LSEQ) * DI + d;
    const float* bc = g_dbc + (size_t)b * LSEQ * DBCW;

    float dlt = g_delta[idx], uu = g_u[idx];
    float B0 = bc[DTR + 2 * j],      B1 = bc[DTR + 2 * j + 1];
    float C0 = bc[DTR + DS + 2 * j], C1 = bc[DTR + DS + 2 * j + 1];

    for (int t = 0; t < LSEQ; t++) {
        float dltn = 0.f, uun = 0.f, B0n = 0.f, B1n = 0.f, C0n = 0.f, C1n = 0.f;
        if (t + 1 < LSEQ) {
            dltn = g_delta[idx + DI]; uun = g_u[idx + DI];
            const float* bcn = bc + DBCW;
            B0n = bcn[DTR + 2 * j];      B1n = bcn[DTR + 2 * j + 1];
            C0n = bcn[DTR + DS + 2 * j]; C1n = bcn[DTR + DS + 2 * j + 1];
        }
        float dA0 = __expf(dlt * A0), dA1 = __expf(dlt * A1);
        float du  = dlt * uu;
        s0 = s0 * dA0 + du * B0;
        s1 = s1 * dA1 + du * B1;
        float p = s0 * C0 + s1 * C1;
        p += __shfl_xor_sync(0xffffffffu, p, 1);
        p += __shfl_xor_sync(0xffffffffu, p, 2);
        p += __shfl_xor_sync(0xffffffffu, p, 4);
        if (j == 0) g_xi[idx] = p + uu * Dd;
        idx += DI; bc += DBCW;
        dlt = dltn; uu = uun; B0 = B0n; B1 = B1n; C0 = C0n; C1 = C1n;
    }
}

// ---------------- launch (kernel launches ONLY) ----------------
extern "C" void kernel_launch(void* const* d_in, const int* in_sizes, int n_in,
                              void* d_out, int out_size) {
    (void)in_sizes; (void)n_in; (void)out_size;
    const float* x         = (const float*)d_in[0];
    const float* norm_w    = (const float*)d_in[1];
    const float* in_proj_w = (const float*)d_in[2];
    const float* conv_w    = (const float*)d_in[3];
    const float* conv_b    = (const float*)d_in[4];
    const float* x_proj_w  = (const float*)d_in[5];
    const float* dt_proj_w = (const float*)d_in[6];
    const float* dt_proj_b = (const float*)d_in[7];
    const float* A_log     = (const float*)d_in[8];
    const float* Dp        = (const float*)d_in[9];
    const float* out_proj_w= (const float*)d_in[10];
    float* out = (float*)d_out;

    // 1) rms scales
    rms_kernel<<<NTOK, 256>>>(x);

    // 2) in_proj: [8192,1024] x [4096,1024]^T, rmsnorm fold -> split g_xi / g_z
    gemm_tf32<0, 1, 0><<<dim3(4096 / 64, NTOK / 128), 256>>>(
        x, in_proj_w, 4096, 1024, 1024, norm_w, nullptr, 0, nullptr);

    // 3) conv + silu: g_xi -> g_u
    conv_silu_kernel<<<dim3(DI / 256, LSEQ / 8, BATCH), 256>>>(conv_w, conv_b);

    // 4) x_proj: g_u [8192,2048] x [96,2048]^T -> g_dbc
    gemm_tf32<1, 0, 1><<<dim3(2, NTOK / 128), 256>>>(
        nullptr, x_proj_w, 96, 2048, 2048, nullptr, nullptr, 0, nullptr);

    // 5) dt_proj: g_dbc[:, :64] (lda=96) x [2048,64]^T, softplus(+b) -> g_delta
    gemm_tf32<2, 0, 2><<<dim3(2048 / 64, NTOK / 128), 256>>>(
        nullptr, dt_proj_w, 2048, 64, DBCW, nullptr, nullptr, 0, dt_proj_b);

    // 6) selective scan -> y in g_xi
    scan_kernel<<<dim3(DI / 32, BATCH), 256>>>(A_log, Dp);

    // 7) out_proj: (y * silu(g_z)) x [1024,2048]^T + x -> out
    gemm_tf32<3, 2, 3><<<dim3(1024 / 64, NTOK / 128), 256>>>(
        nullptr, out_proj_w, 1024, 2048, 2048, nullptr, out, 1024, x);
}

// round 17
// speedup vs baseline: 1.1024x; 1.1024x over previous
#include <cuda_runtime.h>
#include <cuda_bf16.h>
#include <mma.h>
#include <math.h>

using namespace nvcuda;

#define NTOK   8192
#define DMODEL 1024
#define DI     2048
#define DS     16
#define LSEQ   2048
#define BATCH  4
#define DTR    64
#define DBCW   96

// ---------------- scratch: proven set ----------------
__device__ __align__(256) float g_scale[NTOK];
__device__ __align__(256) float g_xi   [(size_t)NTOK * DI];    // xi -> later y
__device__ __align__(256) float g_u    [(size_t)NTOK * DI];    // silu(conv)
__device__ __align__(256) float g_z    [(size_t)NTOK * DI];    // gate branch
__device__ __align__(256) float g_dbc  [(size_t)NTOK * DBCW];  // x_proj out
__device__ __align__(256) float g_delta[(size_t)NTOK * DI];    // softplus

__device__ __forceinline__ float siluf(float v) { return v / (1.f + __expf(-v)); }

// ---------------- RMS scale per token ----------------
__global__ void rms_kernel(const float* __restrict__ x) {
    int t = blockIdx.x;
    const float* row = x + (size_t)t * DMODEL;
    float s = 0.f;
    for (int i = threadIdx.x; i < DMODEL; i += 256) { float v = row[i]; s += v * v; }
    #pragma unroll
    for (int o = 16; o; o >>= 1) s += __shfl_xor_sync(0xffffffffu, s, o);
    __shared__ float sm[8];
    if ((threadIdx.x & 31) == 0) sm[threadIdx.x >> 5] = s;
    __syncthreads();
    if (threadIdx.x == 0) {
        float tot = 0.f;
        #pragma unroll
        for (int i = 0; i < 8; i++) tot += sm[i];
        g_scale[t] = rsqrtf(tot / (float)DMODEL + 1e-5f);
    }
}

// ---------------- zero g_dbc (for split-K atomic accumulation) ----------------
__global__ void zero_dbc_kernel() {
    size_t i = ((size_t)blockIdx.x * 256 + threadIdx.x) * 4;
    *reinterpret_cast<float4*>(g_dbc + i) = make_float4(0.f, 0.f, 0.f, 0.f);
}

// ---------------- tf32 wmma GEMM (round-13 structure, tf32 at staging) ----------------
// C = A(M x Ktot) * B(N x Ktot)^T ; z-block covers K-chunk [z*Kc, (z+1)*Kc)
// SRC: 0 ext | 1 g_u | 2 g_dbc | 3 g_xi
// AMODE: 0 plain | 1 A*g_scale[row]*colw (rmsnorm) | 2 A*silu(g_z) (gate)
// EPI: 0 split -> g_xi / g_z | 1 atomicAdd -> g_dbc | 2 softplus(acc+epivec[c]) -> g_delta
//      3 acc + epivec[r*ldc+c] -> outext
template<int SRC, int AMODE, int EPI>
__global__ void __launch_bounds__(256)
gemm_tf32(const float* __restrict__ Aext, const float* __restrict__ Bw,
          int N, int Kc, int Ktot, int lda,
          const float* __restrict__ colw,
          float* __restrict__ outext,
          int ldc, const float* __restrict__ epivec)
{
    constexpr int BM = 128, BN = 64, BK = 32, LDT = 36;
    __shared__ __align__(16) float sPool[(BM + BN) * LDT];   // 27648 B
    float* sA = sPool;                 // 128 x 36
    float* sB = sPool + BM * LDT;      // 64 x 36
    float* sC = sPool;                 // epilogue alias: 128 x 32

    const float* A = (SRC == 0) ? Aext : (SRC == 1) ? g_u : (SRC == 2) ? g_dbc : g_xi;

    const int tid = threadIdx.x;
    const int bm = blockIdx.y, bn = blockIdx.x;
    const int kb = blockIdx.z * Kc;
    const int warp = tid >> 5;
    const int wm = warp >> 1, wn = warp & 1;   // 4 x 2 warps, each 32x32

    wmma::fragment<wmma::accumulator, 16, 16, 8, float> acc[2][2];
    #pragma unroll
    for (int i = 0; i < 2; i++)
        #pragma unroll
        for (int j = 0; j < 2; j++) wmma::fill_fragment(acc[i][j], 0.f);

    // A staging: row = tid>>1 (0..127), 16 cols at (tid&1)*16
    const int ar = tid >> 1;
    const int ac = (tid & 1) * 16;
    const int argr = bm * BM + ar;
    const float rs = (AMODE == 1) ? g_scale[argr] : 0.f;
    const float* aRow = A + (size_t)argr * lda;
    const float* zRow = (AMODE == 2) ? (g_z + (size_t)argr * lda) : nullptr;
    // B staging: thread covers 2 float4 chunks q = tid*2+{0,1}
    const int bn0 = (tid * 2) >> 3,     bc0 = ((tid * 2) & 7) * 4;
    const int bn1 = (tid * 2 + 1) >> 3, bc1 = ((tid * 2 + 1) & 7) * 4;
    const int ngc0 = (bn * BN + bn0 < N) ? bn * BN + bn0 : N - 1;
    const int ngc1 = (bn * BN + bn1 < N) ? bn * BN + bn1 : N - 1;
    const float* bRow0 = Bw + (size_t)ngc0 * Ktot;
    const float* bRow1 = Bw + (size_t)ngc1 * Ktot;

    const int KT = Kc / BK;
    for (int kt = 0; kt < KT; kt++) {
        const int k0 = kb + kt * BK;
        // stage A (fused preprocessing + tf32 convert)
        #pragma unroll
        for (int i = 0; i < 4; i++) {
            int c = ac + i * 4;
            float4 v = *reinterpret_cast<const float4*>(aRow + k0 + c);
            if (AMODE == 1) {
                float4 w = *reinterpret_cast<const float4*>(colw + k0 + c);
                v.x *= rs * w.x; v.y *= rs * w.y; v.z *= rs * w.z; v.w *= rs * w.w;
            } else if (AMODE == 2) {
                float4 z = *reinterpret_cast<const float4*>(zRow + k0 + c);
                v.x *= siluf(z.x); v.y *= siluf(z.y);
                v.z *= siluf(z.z); v.w *= siluf(z.w);
            }
            v.x = wmma::__float_to_tf32(v.x); v.y = wmma::__float_to_tf32(v.y);
            v.z = wmma::__float_to_tf32(v.z); v.w = wmma::__float_to_tf32(v.w);
            *reinterpret_cast<float4*>(&sA[ar * LDT + c]) = v;
        }
        // stage B (tf32 convert at staging)
        {
            float4 u = *reinterpret_cast<const float4*>(bRow0 + k0 + bc0);
            u.x = wmma::__float_to_tf32(u.x); u.y = wmma::__float_to_tf32(u.y);
            u.z = wmma::__float_to_tf32(u.z); u.w = wmma::__float_to_tf32(u.w);
            *reinterpret_cast<float4*>(&sB[bn0 * LDT + bc0]) = u;
            float4 t = *reinterpret_cast<const float4*>(bRow1 + k0 + bc1);
            t.x = wmma::__float_to_tf32(t.x); t.y = wmma::__float_to_tf32(t.y);
            t.z = wmma::__float_to_tf32(t.z); t.w = wmma::__float_to_tf32(t.w);
            *reinterpret_cast<float4*>(&sB[bn1 * LDT + bc1]) = t;
        }
        __syncthreads();

        #pragma unroll
        for (int kk = 0; kk < BK; kk += 8) {
            wmma::fragment<wmma::matrix_a, 16, 16, 8, wmma::precision::tf32, wmma::row_major> fa[2];
            wmma::fragment<wmma::matrix_b, 16, 16, 8, wmma::precision::tf32, wmma::col_major> fb[2];
            #pragma unroll
            for (int i = 0; i < 2; i++)
                wmma::load_matrix_sync(fa[i], &sA[(wm * 32 + i * 16) * LDT + kk], LDT);
            #pragma unroll
            for (int j = 0; j < 2; j++)
                wmma::load_matrix_sync(fb[j], &sB[(wn * 32 + j * 16) * LDT + kk], LDT);
            #pragma unroll
            for (int i = 0; i < 2; i++)
                #pragma unroll
                for (int j = 0; j < 2; j++)
                    wmma::mma_sync(acc[i][j], fa[i], fb[j], acc[i][j]);
        }
        __syncthreads();
    }

    // epilogue: two 32-col chunks through aliased sC (128 x 32)
    #pragma unroll
    for (int h = 0; h < 2; h++) {
        if (wn == h) {
            #pragma unroll
            for (int i = 0; i < 2; i++)
                #pragma unroll
                for (int j = 0; j < 2; j++)
                    wmma::store_matrix_sync(&sC[(wm * 32 + i * 16) * 32 + j * 16],
                                            acc[i][j], 32, wmma::mem_row_major);
        }
        __syncthreads();
        for (int e = tid; e < BM * 32; e += 256) {
            int r = e >> 5, c = e & 31;
            int rg = bm * BM + r;
            int cg = bn * BN + h * 32 + c;
            if (cg < N) {
                float v = sC[e];
                if (EPI == 0) {
                    if (cg < DI) g_xi[(size_t)rg * DI + cg] = v;
                    else         g_z [(size_t)rg * DI + cg - DI] = v;
                } else if (EPI == 1) {
                    atomicAdd(&g_dbc[(size_t)rg * DBCW + cg], v);
                } else if (EPI == 2) {
                    float t2 = v + epivec[cg];
                    g_delta[(size_t)rg * DI + cg] = (t2 > 20.f) ? t2 : log1pf(__expf(t2));
                } else {
                    outext[(size_t)rg * ldc + cg] = v + epivec[(size_t)rg * ldc + cg];
                }
            }
        }
        __syncthreads();
    }
}

// ---------------- causal depthwise conv (k=4) + bias + SiLU ----------------
__global__ void conv_silu_kernel(const float* __restrict__ cw, const float* __restrict__ cb) {
    int c  = blockIdx.x * 256 + threadIdx.x;
    int b  = blockIdx.z;
    int t0 = blockIdx.y * 8;
    float w0 = cw[c * 4 + 0], w1 = cw[c * 4 + 1], w2 = cw[c * 4 + 2], w3 = cw[c * 4 + 3];
    float bias = cb[c];
    float v[11];
    #pragma unroll
    for (int q = 0; q < 11; q++) {
        int t = t0 - 3 + q;
        v[q] = (t >= 0) ? g_xi[((size_t)(b * LSEQ + t)) * DI + c] : 0.f;
    }
    #pragma unroll
    for (int tt = 0; tt < 8; tt++) {
        float o = w0 * v[tt] + w1 * v[tt + 1] + w2 * v[tt + 2] + w3 * v[tt + 3] + bias;
        g_u[((size_t)(b * LSEQ + t0 + tt)) * DI + c] = siluf(o);
    }
}

// ---------------- selective scan (y -> g_xi) ----------------
__global__ void scan_kernel(const float* __restrict__ A_log, const float* __restrict__ Dp) {
    int b    = blockIdx.y;
    int lane = threadIdx.x & 31, warp = threadIdx.x >> 5;
    int chan_local = warp * 4 + (lane >> 3);
    int j = lane & 7;
    int d = blockIdx.x * 32 + chan_local;

    float A0 = -__expf(A_log[d * DS + 2 * j]);
    float A1 = -__expf(A_log[d * DS + 2 * j + 1]);
    float Dd = Dp[d];
    float s0 = 0.f, s1 = 0.f;

    size_t idx = ((size_t)b * LSEQ) * DI + d;
    const float* bc = g_dbc + (size_t)b * LSEQ * DBCW;

    float dlt = g_delta[idx], uu = g_u[idx];
    float B0 = bc[DTR + 2 * j],      B1 = bc[DTR + 2 * j + 1];
    float C0 = bc[DTR + DS + 2 * j], C1 = bc[DTR + DS + 2 * j + 1];

    for (int t = 0; t < LSEQ; t++) {
        float dltn = 0.f, uun = 0.f, B0n = 0.f, B1n = 0.f, C0n = 0.f, C1n = 0.f;
        if (t + 1 < LSEQ) {
            dltn = g_delta[idx + DI]; uun = g_u[idx + DI];
            const float* bcn = bc + DBCW;
            B0n = bcn[DTR + 2 * j];      B1n = bcn[DTR + 2 * j + 1];
            C0n = bcn[DTR + DS + 2 * j]; C1n = bcn[DTR + DS + 2 * j + 1];
        }
        float dA0 = __expf(dlt * A0), dA1 = __expf(dlt * A1);
        float du  = dlt * uu;
        s0 = s0 * dA0 + du * B0;
        s1 = s1 * dA1 + du * B1;
        float p = s0 * C0 + s1 * C1;
        p += __shfl_xor_sync(0xffffffffu, p, 1);
        p += __shfl_xor_sync(0xffffffffu, p, 2);
        p += __shfl_xor_sync(0xffffffffu, p, 4);
        if (j == 0) g_xi[idx] = p + uu * Dd;
        idx += DI; bc += DBCW;
        dlt = dltn; uu = uun; B0 = B0n; B1 = B1n; C0 = C0n; C1 = C1n;
    }
}

// ---------------- launch (kernel launches ONLY) ----------------
extern "C" void kernel_launch(void* const* d_in, const int* in_sizes, int n_in,
                              void* d_out, int out_size) {
    (void)in_sizes; (void)n_in; (void)out_size;
    const float* x         = (const float*)d_in[0];
    const float* norm_w    = (const float*)d_in[1];
    const float* in_proj_w = (const float*)d_in[2];
    const float* conv_w    = (const float*)d_in[3];
    const float* conv_b    = (const float*)d_in[4];
    const float* x_proj_w  = (const float*)d_in[5];
    const float* dt_proj_w = (const float*)d_in[6];
    const float* dt_proj_b = (const float*)d_in[7];
    const float* A_log     = (const float*)d_in[8];
    const float* Dp        = (const float*)d_in[9];
    const float* out_proj_w= (const float*)d_in[10];
    float* out = (float*)d_out;

    // 1) rms scales
    rms_kernel<<<NTOK, 256>>>(x);

    // 2) in_proj: rmsnorm fold -> split g_xi / g_z
    gemm_tf32<0, 1, 0><<<dim3(4096 / 64, NTOK / 128, 1), 256>>>(
        x, in_proj_w, 4096, 1024, 1024, 1024, norm_w, nullptr, 0, nullptr);

    // 3) conv + silu: g_xi -> g_u
    conv_silu_kernel<<<dim3(DI / 256, LSEQ / 8, BATCH), 256>>>(conv_w, conv_b);

    // 4a) zero g_dbc for split-K accumulation
    zero_dbc_kernel<<<(NTOK * DBCW) / 1024, 256>>>();

    // 4b) x_proj: split-K x4, atomicAdd -> g_dbc
    gemm_tf32<1, 0, 1><<<dim3(2, NTOK / 128, 4), 256>>>(
        nullptr, x_proj_w, 96, 512, 2048, 2048, nullptr, nullptr, 0, nullptr);

    // 5) dt_proj: g_dbc[:, :64] (lda=96), softplus(+b) -> g_delta
    gemm_tf32<2, 0, 2><<<dim3(2048 / 64, NTOK / 128, 1), 256>>>(
        nullptr, dt_proj_w, 2048, 64, 64, DBCW, nullptr, nullptr, 0, dt_proj_b);

    // 6) selective scan -> y in g_xi
    scan_kernel<<<dim3(DI / 32, BATCH), 256>>>(A_log, Dp);

    // 7) out_proj: (y * silu(g_z)) + x -> out
    gemm_tf32<3, 2, 3><<<dim3(1024 / 64, NTOK / 128, 1), 256>>>(
        nullptr, out_proj_w, 1024, 2048, 2048, 2048, nullptr, out, 1024, x);
}